// round 2
// baseline (speedup 1.0000x reference)
#include <cuda_runtime.h>
#include <cuda_bf16.h>

typedef unsigned long long u64;

#define SEQL   512
#define BATCH  32
#define HDIM   1024
#define VOCAB  8192
#define ML     (BATCH*SEQL)              /* 16384 */
#define LOGITS_ELEMS 134217728           /* 32*512*8192 */

// ---------------- scratch (cudaMalloc forbidden) ----------------
__device__ float g_pre[ML*HDIM];         // 64 MB, layout [t][b][h]
__device__ float g_hout[ML*HDIM];        // 64 MB, layout [t][b][h]
__device__ int   g_map1[ML];             // row m=t*32+b -> embedding id
__device__ int   g_map3[ML];             // row m=b*512+t -> t*32+b
__device__ int   g_is64;

// ---------------- f32x2 helpers ----------------
__device__ __forceinline__ u64 ffma2(u64 a, u64 b, u64 c){
    u64 d; asm("fma.rn.f32x2 %0, %1, %2, %3;" : "=l"(d) : "l"(a), "l"(b), "l"(c)); return d;
}
__device__ __forceinline__ u64 pack2(float x, float y){
    u64 r; unsigned xi = __float_as_uint(x), yi = __float_as_uint(y);
    asm("mov.b64 %0, {%1, %2};" : "=l"(r) : "r"(xi), "r"(yi)); return r;
}
__device__ __forceinline__ float2 unpack2(u64 v){
    unsigned lo, hi; asm("mov.b64 {%0, %1}, %2;" : "=r"(lo), "=r"(hi) : "l"(v));
    return make_float2(__uint_as_float(lo), __uint_as_float(hi));
}

// ---------------- id dtype detection (int32 vs int64) ----------------
__global__ void detect_kernel(const long long* __restrict__ x){
    if (threadIdx.x == 0 && blockIdx.x == 0){
        int ok = 1;
        #pragma unroll
        for (int i = 0; i < 16; i++){
            long long v = x[i];
            if (v < 0 || v >= VOCAB) ok = 0;
        }
        g_is64 = ok;
    }
}

__global__ void build_maps(const void* __restrict__ xraw){
    int i = blockIdx.x * blockDim.x + threadIdx.x;
    if (i >= ML) return;
    int is64 = g_is64;
    int t = i >> 5, b = i & 31;
    long long id = is64 ? ((const long long*)xraw)[b*SEQL + t]
                        : (long long)((const int*)xraw)[b*SEQL + t];
    g_map1[i] = (int)id;
    int b3 = i >> 9, t3 = i & 511;
    g_map3[i] = t3*32 + b3;
}

// ---------------- generic NT GEMM with gathered A rows ----------------
// C[m][n] = sum_k A[amap[m]][k] * B[n][k], K=1024, rows of A/B are 1024 floats.
// BM=BN=128, BK=16, 256 threads, 8x8 microtile, f32x2 FMAs, register prefetch.
__global__ __launch_bounds__(256,2) void gemm_nt(
    const float* __restrict__ A, const float* __restrict__ B,
    float* __restrict__ C, const int* __restrict__ amap, int ldc)
{
    __shared__ float As[16][132];
    __shared__ float Bs[16][132];
    __shared__ int sMap[128];
    const int tid = threadIdx.x;
    const int bn = blockIdx.x, bm = blockIdx.y;
    if (tid < 128) sMap[tid] = amap[bm*128 + tid];
    __syncthreads();

    const int tx = tid & 15, ty = tid >> 4;
    const int nBase = bn * 128;
    const int m0 = tid >> 2;                 // 0..63
    const int k0 = (tid & 3) << 2;           // 0,4,8,12
    const int m1 = m0 + 64;

    u64 acc[8][4];
    #pragma unroll
    for (int r = 0; r < 8; r++)
        #pragma unroll
        for (int j = 0; j < 4; j++) acc[r][j] = 0ull;

    float4 pa0, pa1, pb0, pb1;
    pa0 = *(const float4*)(A + (size_t)sMap[m0]*HDIM + k0);
    pa1 = *(const float4*)(A + (size_t)sMap[m1]*HDIM + k0);
    pb0 = *(const float4*)(B + (size_t)(nBase + m0)*HDIM + k0);
    pb1 = *(const float4*)(B + (size_t)(nBase + m1)*HDIM + k0);

    for (int kt = 0; kt < 1024; kt += 16){
        // stage current tile
        As[k0  ][m0]=pa0.x; As[k0+1][m0]=pa0.y; As[k0+2][m0]=pa0.z; As[k0+3][m0]=pa0.w;
        As[k0  ][m1]=pa1.x; As[k0+1][m1]=pa1.y; As[k0+2][m1]=pa1.z; As[k0+3][m1]=pa1.w;
        Bs[k0  ][m0]=pb0.x; Bs[k0+1][m0]=pb0.y; Bs[k0+2][m0]=pb0.z; Bs[k0+3][m0]=pb0.w;
        Bs[k0  ][m1]=pb1.x; Bs[k0+1][m1]=pb1.y; Bs[k0+2][m1]=pb1.z; Bs[k0+3][m1]=pb1.w;
        __syncthreads();

        // prefetch next tile into registers
        if (kt + 16 < 1024){
            int kn = kt + 16;
            pa0 = *(const float4*)(A + (size_t)sMap[m0]*HDIM + kn + k0);
            pa1 = *(const float4*)(A + (size_t)sMap[m1]*HDIM + kn + k0);
            pb0 = *(const float4*)(B + (size_t)(nBase + m0)*HDIM + kn + k0);
            pb1 = *(const float4*)(B + (size_t)(nBase + m1)*HDIM + kn + k0);
        }

        #pragma unroll
        for (int k = 0; k < 16; k++){
            ulonglong2 bq0 = *(const ulonglong2*)&Bs[k][tx*8];
            ulonglong2 bq1 = *(const ulonglong2*)&Bs[k][tx*8 + 4];
            float4 a0 = *(const float4*)&As[k][ty*8];
            float4 a1 = *(const float4*)&As[k][ty*8 + 4];
            float av[8] = {a0.x,a0.y,a0.z,a0.w,a1.x,a1.y,a1.z,a1.w};
            #pragma unroll
            for (int r = 0; r < 8; r++){
                u64 pa = pack2(av[r], av[r]);
                acc[r][0] = ffma2(pa, bq0.x, acc[r][0]);
                acc[r][1] = ffma2(pa, bq0.y, acc[r][1]);
                acc[r][2] = ffma2(pa, bq1.x, acc[r][2]);
                acc[r][3] = ffma2(pa, bq1.y, acc[r][3]);
            }
        }
        __syncthreads();
    }

    #pragma unroll
    for (int r = 0; r < 8; r++){
        float v[8];
        #pragma unroll
        for (int j = 0; j < 4; j++){
            float2 f = unpack2(acc[r][j]);
            v[2*j] = f.x; v[2*j+1] = f.y;
        }
        float* crow = C + (size_t)(bm*128 + ty*8 + r) * ldc + nBase + tx*8;
        *(float4*)(crow)     = make_float4(v[0], v[1], v[2], v[3]);
        *(float4*)(crow + 4) = make_float4(v[4], v[5], v[6], v[7]);
    }
}

// ---------------- recurrent step ----------------
// h_t[b][c] = tanh(pre_t[b][c] + sum_k hprev[b][k]*W_h[c][k])
// Grid 128 = 4 batch-groups(8 batches) x 32 col-groups(32 cols).
// 256 threads: warp = batch, lane = column. K tiled by 256.
__global__ __launch_bounds__(256) void step_kernel(
    const float* __restrict__ hprev, const float* __restrict__ W_h,
    const float* __restrict__ pre_t, float* __restrict__ hout_t)
{
    __shared__ float4 ws4[32][65];   // W_h slice [32 cols][64 float4 + pad]
    __shared__ float4 sh4[8][65];    // h slice   [8 batches][64 float4 + pad]
    const int tid = threadIdx.x;
    const int bg = blockIdx.x >> 5, cg = blockIdx.x & 31;
    const int warp = tid >> 5, lane = tid & 31;

    u64 acc0 = 0ull, acc1 = 0ull;
    for (int kt = 0; kt < 1024; kt += 256){
        #pragma unroll
        for (int i = 0; i < 8; i++){
            int idx = tid + i*256;
            int cr = idx >> 6, q = idx & 63;
            ws4[cr][q] = *(const float4*)(W_h + (size_t)(cg*32 + cr)*HDIM + kt + q*4);
        }
        #pragma unroll
        for (int i = 0; i < 2; i++){
            int idx = tid + i*256;
            int br = idx >> 6, q = idx & 63;
            sh4[br][q] = *(const float4*)(hprev + (size_t)(bg*8 + br)*HDIM + kt + q*4);
        }
        __syncthreads();
        #pragma unroll
        for (int q = 0; q < 64; q++){
            ulonglong2 wq = *(const ulonglong2*)&ws4[lane][q];
            ulonglong2 hq = *(const ulonglong2*)&sh4[warp][q];   // broadcast
            acc0 = ffma2(wq.x, hq.x, acc0);
            acc1 = ffma2(wq.y, hq.y, acc1);
        }
        __syncthreads();
    }
    float2 s0 = unpack2(acc0), s1 = unpack2(acc1);
    float dot = (s0.x + s0.y) + (s1.x + s1.y);
    int b = bg*8 + warp, c = cg*32 + lane;
    hout_t[b*HDIM + c] = tanhf(dot + pre_t[b*HDIM + c]);
}

__global__ void copy_hidden(float* __restrict__ dst){
    int i = blockIdx.x * blockDim.x + threadIdx.x;
    dst[i] = g_hout[(size_t)(511*32)*HDIM + i];
}

extern "C" void kernel_launch(void* const* d_in, const int* in_sizes, int n_in,
                              void* d_out, int out_size) {
    const void*  x      = d_in[0];
    const float* hidden = (const float*)d_in[1];
    const float* emb    = (const float*)d_in[2];
    const float* W_h    = (const float*)d_in[3];
    const float* W_e    = (const float*)d_in[4];
    const float* W_o    = (const float*)d_in[5];
    float* out = (float*)d_out;

    float *pre, *hout; int *map1, *map3;
    cudaGetSymbolAddress((void**)&pre,  g_pre);
    cudaGetSymbolAddress((void**)&hout, g_hout);
    cudaGetSymbolAddress((void**)&map1, g_map1);
    cudaGetSymbolAddress((void**)&map3, g_map3);

    detect_kernel<<<1, 32>>>((const long long*)x);
    build_maps<<<64, 256>>>(x);

    // Phase 1: pre = emb[x] @ W_e^T   (M=16384, N=1024)
    gemm_nt<<<dim3(8, 128), 256>>>(emb, W_e, pre, map1, HDIM);

    // Phase 2: sequential scan, one graph node per step
    for (int t = 0; t < SEQL; t++){
        const float* hp = (t == 0) ? hidden : (hout + (size_t)(t-1)*BATCH*HDIM);
        step_kernel<<<128, 256>>>(hp, W_h,
                                  pre  + (size_t)t*BATCH*HDIM,
                                  hout + (size_t)t*BATCH*HDIM);
    }

    // Phase 3: logits = outputs @ W_o^T   (M=16384 rows b*512+t, N=8192)
    gemm_nt<<<dim3(64, 128), 256>>>(hout, W_o, out, map3, VOCAB);

    if (out_size >= LOGITS_ELEMS + BATCH*HDIM)
        copy_hidden<<<32, 1024>>>(out + LOGITS_ELEMS);
}

// round 3
// speedup vs baseline: 1.3982x; 1.3982x over previous
#include <cuda_runtime.h>
#include <cuda_bf16.h>

typedef unsigned long long u64;

#define SEQL   512
#define BATCH  32
#define HDIM   1024
#define VOCAB  8192
#define ML     (BATCH*SEQL)              /* 16384 */
#define LOGITS_ELEMS 134217728           /* 32*512*8192 */

// ---------------- scratch (cudaMalloc forbidden) ----------------
__device__ float g_pre[ML*HDIM];         // 64 MB, layout [t][b][h]
__device__ float g_hout[ML*HDIM];        // 64 MB, layout [t][b][h]
__device__ int   g_map1[ML];             // row m=t*32+b -> embedding id
__device__ int   g_map3[ML];             // row m=b*512+t -> t*32+b
__device__ int   g_is64;
__device__ unsigned g_barcnt;            // persistent-scan barrier counter

// ---------------- f32x2 helpers ----------------
__device__ __forceinline__ u64 ffma2(u64 a, u64 b, u64 c){
    u64 d; asm("fma.rn.f32x2 %0, %1, %2, %3;" : "=l"(d) : "l"(a), "l"(b), "l"(c)); return d;
}
__device__ __forceinline__ u64 pack2(float x, float y){
    u64 r; unsigned xi = __float_as_uint(x), yi = __float_as_uint(y);
    asm("mov.b64 %0, {%1, %2};" : "=l"(r) : "r"(xi), "r"(yi)); return r;
}
__device__ __forceinline__ float2 unpack2(u64 v){
    unsigned lo, hi; asm("mov.b64 {%0, %1}, %2;" : "=r"(lo), "=r"(hi) : "l"(v));
    return make_float2(__uint_as_float(lo), __uint_as_float(hi));
}

// ---------------- id dtype detection (int32 vs int64) ----------------
__global__ void detect_kernel(const long long* __restrict__ x){
    if (threadIdx.x == 0 && blockIdx.x == 0){
        int ok = 1;
        #pragma unroll
        for (int i = 0; i < 16; i++){
            long long v = x[i];
            if (v < 0 || v >= VOCAB) ok = 0;
        }
        g_is64 = ok;
    }
}

__global__ void build_maps(const void* __restrict__ xraw){
    int i = blockIdx.x * blockDim.x + threadIdx.x;
    if (i == 0) g_barcnt = 0u;           // reset scan barrier every replay
    if (i >= ML) return;
    int is64 = g_is64;
    int t = i >> 5, b = i & 31;
    long long id = is64 ? ((const long long*)xraw)[b*SEQL + t]
                        : (long long)((const int*)xraw)[b*SEQL + t];
    g_map1[i] = (int)id;
    int b3 = i >> 9, t3 = i & 511;
    g_map3[i] = t3*32 + b3;
}

// ---------------- generic NT GEMM with gathered A rows ----------------
// C[m][n] = sum_k A[amap[m]][k] * B[n][k], K=1024.
// BM=BN=128, BK=16, 256 threads, 8x8 microtile, f32x2 FMAs, register prefetch.
__global__ __launch_bounds__(256,2) void gemm_nt(
    const float* __restrict__ A, const float* __restrict__ B,
    float* __restrict__ C, const int* __restrict__ amap, int ldc)
{
    __shared__ float As[16][132];
    __shared__ float Bs[16][132];
    __shared__ int sMap[128];
    const int tid = threadIdx.x;
    const int bn = blockIdx.x, bm = blockIdx.y;
    if (tid < 128) sMap[tid] = amap[bm*128 + tid];
    __syncthreads();

    const int tx = tid & 15, ty = tid >> 4;
    const int nBase = bn * 128;
    const int m0 = tid >> 2;
    const int k0 = (tid & 3) << 2;
    const int m1 = m0 + 64;

    u64 acc[8][4];
    #pragma unroll
    for (int r = 0; r < 8; r++)
        #pragma unroll
        for (int j = 0; j < 4; j++) acc[r][j] = 0ull;

    float4 pa0, pa1, pb0, pb1;
    pa0 = *(const float4*)(A + (size_t)sMap[m0]*HDIM + k0);
    pa1 = *(const float4*)(A + (size_t)sMap[m1]*HDIM + k0);
    pb0 = *(const float4*)(B + (size_t)(nBase + m0)*HDIM + k0);
    pb1 = *(const float4*)(B + (size_t)(nBase + m1)*HDIM + k0);

    for (int kt = 0; kt < 1024; kt += 16){
        As[k0  ][m0]=pa0.x; As[k0+1][m0]=pa0.y; As[k0+2][m0]=pa0.z; As[k0+3][m0]=pa0.w;
        As[k0  ][m1]=pa1.x; As[k0+1][m1]=pa1.y; As[k0+2][m1]=pa1.z; As[k0+3][m1]=pa1.w;
        Bs[k0  ][m0]=pb0.x; Bs[k0+1][m0]=pb0.y; Bs[k0+2][m0]=pb0.z; Bs[k0+3][m0]=pb0.w;
        Bs[k0  ][m1]=pb1.x; Bs[k0+1][m1]=pb1.y; Bs[k0+2][m1]=pb1.z; Bs[k0+3][m1]=pb1.w;
        __syncthreads();

        if (kt + 16 < 1024){
            int kn = kt + 16;
            pa0 = *(const float4*)(A + (size_t)sMap[m0]*HDIM + kn + k0);
            pa1 = *(const float4*)(A + (size_t)sMap[m1]*HDIM + kn + k0);
            pb0 = *(const float4*)(B + (size_t)(nBase + m0)*HDIM + kn + k0);
            pb1 = *(const float4*)(B + (size_t)(nBase + m1)*HDIM + kn + k0);
        }

        #pragma unroll
        for (int k = 0; k < 16; k++){
            ulonglong2 bq0 = *(const ulonglong2*)&Bs[k][tx*8];
            ulonglong2 bq1 = *(const ulonglong2*)&Bs[k][tx*8 + 4];
            float4 a0 = *(const float4*)&As[k][ty*8];
            float4 a1 = *(const float4*)&As[k][ty*8 + 4];
            float av[8] = {a0.x,a0.y,a0.z,a0.w,a1.x,a1.y,a1.z,a1.w};
            #pragma unroll
            for (int r = 0; r < 8; r++){
                u64 pa = pack2(av[r], av[r]);
                acc[r][0] = ffma2(pa, bq0.x, acc[r][0]);
                acc[r][1] = ffma2(pa, bq0.y, acc[r][1]);
                acc[r][2] = ffma2(pa, bq1.x, acc[r][2]);
                acc[r][3] = ffma2(pa, bq1.y, acc[r][3]);
            }
        }
        __syncthreads();
    }

    #pragma unroll
    for (int r = 0; r < 8; r++){
        float v[8];
        #pragma unroll
        for (int j = 0; j < 4; j++){
            float2 f = unpack2(acc[r][j]);
            v[2*j] = f.x; v[2*j+1] = f.y;
        }
        float* crow = C + (size_t)(bm*128 + ty*8 + r) * ldc + nBase + tx*8;
        *(float4*)(crow)     = make_float4(v[0], v[1], v[2], v[3]);
        *(float4*)(crow + 4) = make_float4(v[4], v[5], v[6], v[7]);
    }
}

// ---------------- persistent recurrent scan ----------------
// ONE kernel for all 512 steps. 128 CTAs (all co-resident on 152-SM GB300),
// global sense barrier between steps. W_h slice lives in REGISTERS
// (step-invariant): CTA = 32 cols x 8 batches; thread = (col, K-chunk of 128),
// holds 128 W floats as 32 ulonglong2. h_prev broadcast via SMEM (warp lanes
// share h address -> conflict-free broadcast LDS).
__global__ __launch_bounds__(256,1) void scan_kernel(
    const float* __restrict__ hidden0, const float* __restrict__ W_h,
    const float* __restrict__ pre, float* __restrict__ hout)
{
    __shared__ float sh[8*HDIM];           // 32 KB: h_prev for 8 batches
    __shared__ float red[8*8*32];          // 8 KB: partials [ks][b][cp]
    const int tid = threadIdx.x;
    const int bg = blockIdx.x >> 5, cg = blockIdx.x & 31;
    const int cp = tid & 31, ks = tid >> 5;
    const int col = cg*32 + cp;

    // step-invariant W_h[col][ks*128 .. +128) in registers (32 x 16B)
    ulonglong2 wreg[32];
    {
        const ulonglong2* wp = (const ulonglong2*)(W_h + (size_t)col*HDIM + ks*128);
        #pragma unroll
        for (int i = 0; i < 32; i++) wreg[i] = wp[i];
    }

    for (int t = 0; t < SEQL; t++){
        // load h_prev slice (contiguous 32 KB) into SMEM
        const float4* src = (const float4*)((t == 0)
            ? (hidden0 + (size_t)bg*8*HDIM)
            : (hout + ((size_t)(t-1)*BATCH + bg*8)*HDIM));
        float4* dst = (float4*)sh;
        #pragma unroll
        for (int i = 0; i < 8; i++) dst[tid + i*256] = src[tid + i*256];
        __syncthreads();

        u64 acc[8];
        #pragma unroll
        for (int b = 0; b < 8; b++) acc[b] = 0ull;

        const ulonglong2* hb = (const ulonglong2*)sh;  // [b*256 + ks*32 + q]
        #pragma unroll
        for (int q = 0; q < 32; q++){
            ulonglong2 w = wreg[q];
            #pragma unroll
            for (int b = 0; b < 8; b++){
                ulonglong2 h = hb[b*256 + ks*32 + q];   // broadcast LDS.128
                acc[b] = ffma2(w.x, h.x, acc[b]);
                acc[b] = ffma2(w.y, h.y, acc[b]);
            }
        }

        #pragma unroll
        for (int b = 0; b < 8; b++){
            float2 f = unpack2(acc[b]);
            red[(ks*8 + b)*32 + cp] = f.x + f.y;
        }
        __syncthreads();

        // reduce 8 K-chunks; thread tid -> (batch b2 = ks, col c2 = cp)
        {
            const int b2 = ks, c2 = cp;
            float dot = 0.f;
            #pragma unroll
            for (int k2 = 0; k2 < 8; k2++) dot += red[(k2*8 + b2)*32 + c2];
            const int gb = bg*8 + b2;
            const size_t off = ((size_t)t*BATCH + gb)*HDIM + cg*32 + c2;
            hout[off] = tanhf(dot + pre[off]);
        }

        // inter-CTA barrier: all h_t writes visible before any CTA reads them
        __threadfence();
        __syncthreads();
        if (tid == 0){
            atomicAdd(&g_barcnt, 1u);
            const unsigned target = 128u*(unsigned)(t+1);
            while (*(volatile unsigned*)&g_barcnt < target) { }
        }
        __syncthreads();
    }
}

__global__ void copy_hidden(float* __restrict__ dst){
    int i = blockIdx.x * blockDim.x + threadIdx.x;
    dst[i] = g_hout[(size_t)(511*32)*HDIM + i];
}

extern "C" void kernel_launch(void* const* d_in, const int* in_sizes, int n_in,
                              void* d_out, int out_size) {
    const void*  x      = d_in[0];
    const float* hidden = (const float*)d_in[1];
    const float* emb    = (const float*)d_in[2];
    const float* W_h    = (const float*)d_in[3];
    const float* W_e    = (const float*)d_in[4];
    const float* W_o    = (const float*)d_in[5];
    float* out = (float*)d_out;

    float *pre, *hout; int *map1, *map3;
    cudaGetSymbolAddress((void**)&pre,  g_pre);
    cudaGetSymbolAddress((void**)&hout, g_hout);
    cudaGetSymbolAddress((void**)&map1, g_map1);
    cudaGetSymbolAddress((void**)&map3, g_map3);

    detect_kernel<<<1, 32>>>((const long long*)x);
    build_maps<<<64, 256>>>(x);

    // Phase 1: pre = emb[x] @ W_e^T   (M=16384, N=1024)
    gemm_nt<<<dim3(8, 128), 256>>>(emb, W_e, pre, map1, HDIM);

    // Phase 2: persistent scan, all 512 steps in ONE kernel
    scan_kernel<<<128, 256>>>(hidden, W_h, pre, hout);

    // Phase 3: logits = outputs @ W_o^T   (M=16384 rows b*512+t, N=8192)
    gemm_nt<<<dim3(64, 128), 256>>>(hout, W_o, out, map3, VOCAB);

    if (out_size >= LOGITS_ELEMS + BATCH*HDIM)
        copy_hidden<<<32, 1024>>>(out + LOGITS_ELEMS);
}